// round 7
// baseline (speedup 1.0000x reference)
#include <cuda_runtime.h>
#include <cuda_bf16.h>
#include <math.h>
#include <stdint.h>

#define B_   8
#define N_   8192
#define D_   512
#define H_   8
#define BN_ROWS 65536

// ---------------- scratch ----------------
__device__ float g_qkv[(size_t)3 * BN_ROWS * D_];            // [unused q] | k | v fp32
__device__ int8_t g_Xa1[(size_t)BN_ROWS * D_];
__device__ int8_t g_Xa2[(size_t)BN_ROWS * D_];
__device__ float g_sX[BN_ROWS];                              // rowmax/127
__device__ int8_t g_Wb1[1536 * 512];                         // [n][k] Wq|Wk|Wv^T digit1
__device__ int8_t g_Wb2[1536 * 512];
__device__ float g_tB[1536];                                 // colmax/127
__device__ __nv_bfloat16 g_qsh[(size_t)BN_ROWS * D_];        // q_n split
__device__ __nv_bfloat16 g_qsl[(size_t)BN_ROWS * D_];
__device__ float g_biasC[1536];
__device__ float g_kvp[(size_t)64 * 8 * 4096];
__device__ __nv_bfloat16 g_Mth[(size_t)B_ * 512 * 512];      // Mt[b][d][k] hi
__device__ __nv_bfloat16 g_Mtl[(size_t)B_ * 512 * 512];

// ---------------- helpers ----------------
__device__ __forceinline__ uint32_t smem_u32(const void* p) {
    uint32_t a;
    asm("{ .reg .u64 t; cvta.to.shared.u64 t, %1; cvt.u32.u64 %0, t; }" : "=r"(a) : "l"(p));
    return a;
}
__device__ __forceinline__ void ldsm4(uint32_t* r, uint32_t a) {
    asm volatile("ldmatrix.sync.aligned.m8n8.x4.shared.b16 {%0,%1,%2,%3}, [%4];"
                 : "=r"(r[0]), "=r"(r[1]), "=r"(r[2]), "=r"(r[3]) : "r"(a));
}
__device__ __forceinline__ void mma16816(float* c, const uint32_t* a, const uint32_t* b) {
    asm volatile(
        "mma.sync.aligned.m16n8k16.row.col.f32.bf16.bf16.f32 "
        "{%0,%1,%2,%3}, {%4,%5,%6,%7}, {%8,%9}, {%0,%1,%2,%3};"
        : "+f"(c[0]), "+f"(c[1]), "+f"(c[2]), "+f"(c[3])
        : "r"(a[0]), "r"(a[1]), "r"(a[2]), "r"(a[3]), "r"(b[0]), "r"(b[1]));
}
__device__ __forceinline__ void imma16832(int* c, const uint32_t* a, const uint32_t* b) {
    asm volatile(
        "mma.sync.aligned.m16n8k32.row.col.s32.s8.s8.s32 "
        "{%0,%1,%2,%3}, {%4,%5,%6,%7}, {%8,%9}, {%0,%1,%2,%3};"
        : "+r"(c[0]), "+r"(c[1]), "+r"(c[2]), "+r"(c[3])
        : "r"(a[0]), "r"(a[1]), "r"(a[2]), "r"(a[3]), "r"(b[0]), "r"(b[1]));
}
#define CPA(d, s) asm volatile("cp.async.cg.shared.global [%0], [%1], 16;" :: "r"(d), "l"(s))
#define CPC()     asm volatile("cp.async.commit_group;" ::: "memory")

__device__ __forceinline__ void split1(float x, __nv_bfloat16& h, __nv_bfloat16& l) {
    h = __float2bfloat16(x);
    l = __float2bfloat16(x - __bfloat162float(h));
}

// int8 GEMM smem: 4 arrays (A1,A2,B1,B2), 128 rows x 64B (+pad to 80B)
#define IA1_O 0u
#define IA2_O 10240u
#define IB1_O 20480u
#define IB2_O 30720u
#define ISTAGE_B 40960u
#define IMMA_SMEM (2 * 40960)

// bf16 final GEMM smem (R6 layout): k-chunk 32, rows 80B
#define AH_O  0u
#define AL_O  10240u
#define BH_O  20480u
#define BL_O  30720u
#define STAGE_B 40960u
#define HMMA_SMEM (2 * 40960)

// =====================================================================
// quant_x: per-row 2-digit int8 quantization of X. warp per row.
// =====================================================================
__global__ __launch_bounds__(256) void quant_x_kernel(const float* __restrict__ X)
{
    const int warp = threadIdx.x >> 5, lane = threadIdx.x & 31;
    const size_t row = (size_t)blockIdx.x * 8 + warp;
    const float* xr = X + row * 512 + lane * 16;
    float v[16];
    #pragma unroll
    for (int j = 0; j < 4; ++j) {
        float4 t = *reinterpret_cast<const float4*>(xr + j * 4);
        v[j * 4] = t.x; v[j * 4 + 1] = t.y; v[j * 4 + 2] = t.z; v[j * 4 + 3] = t.w;
    }
    float m = 0.f;
    #pragma unroll
    for (int j = 0; j < 16; ++j) m = fmaxf(m, fabsf(v[j]));
    #pragma unroll
    for (int s = 16; s >= 1; s >>= 1) m = fmaxf(m, __shfl_xor_sync(0xffffffffu, m, s));
    m = fmaxf(m, 1e-20f);
    const float invs = 127.0f / m;
    if (lane == 0) g_sX[row] = m * (1.0f / 127.0f);
    uint32_t w1[4] = {0, 0, 0, 0}, w2[4] = {0, 0, 0, 0};
    #pragma unroll
    for (int j = 0; j < 16; ++j) {
        float t = v[j] * invs;
        float a1 = rintf(t);
        float a2 = rintf((t - a1) * 254.0f);
        w1[j >> 2] |= ((uint32_t)(uint8_t)(int8_t)(int)a1) << ((j & 3) * 8);
        w2[j >> 2] |= ((uint32_t)(uint8_t)(int8_t)(int)a2) << ((j & 3) * 8);
    }
    const size_t o = row * 512 + lane * 16;
    *reinterpret_cast<uint4*>(&g_Xa1[o]) = make_uint4(w1[0], w1[1], w1[2], w1[3]);
    *reinterpret_cast<uint4*>(&g_Xa2[o]) = make_uint4(w2[0], w2[1], w2[2], w2[3]);
}

// =====================================================================
// quant_w: per output-col (row of W^T) 2-digit int8 quantization. warp per n.
// =====================================================================
__global__ __launch_bounds__(256) void quant_w_kernel(
    const float* __restrict__ Wq, const float* __restrict__ Wk, const float* __restrict__ Wv)
{
    const int warp = threadIdx.x >> 5, lane = threadIdx.x & 31;
    const int n = blockIdx.x * 8 + warp;
    const float* W = (n < 512) ? Wq : (n < 1024) ? Wk : Wv;
    const int nn = n & 511;
    float v[16];
    #pragma unroll
    for (int j = 0; j < 16; ++j) v[j] = W[(size_t)(lane + 32 * j) * 512 + nn];
    float m = 0.f;
    #pragma unroll
    for (int j = 0; j < 16; ++j) m = fmaxf(m, fabsf(v[j]));
    #pragma unroll
    for (int s = 16; s >= 1; s >>= 1) m = fmaxf(m, __shfl_xor_sync(0xffffffffu, m, s));
    m = fmaxf(m, 1e-20f);
    const float invs = 127.0f / m;
    if (lane == 0) g_tB[n] = m * (1.0f / 127.0f);
    #pragma unroll
    for (int j = 0; j < 16; ++j) {
        float t = v[j] * invs;
        float b1 = rintf(t);
        float b2 = rintf((t - b1) * 254.0f);
        const size_t o = (size_t)n * 512 + lane + 32 * j;
        g_Wb1[o] = (int8_t)(int)b1;
        g_Wb2[o] = (int8_t)(int)b2;
    }
}

// =====================================================================
// pack_bias
// =====================================================================
__global__ void pack_bias_kernel(
    const float* __restrict__ bq, const float* __restrict__ bk, const float* __restrict__ bv)
{
    const int i = blockIdx.x * 256 + threadIdx.x;
    g_biasC[i] = (i < 512) ? bq[i] : (i < 1024) ? bk[i - 512] : bv[i - 1024];
}

// =====================================================================
// IMMA QKV GEMM: CTA 128x128, warp 64x32 (2M x 4N), k-chunk 64 (2 k32 steps).
// C = X @ W^T via 2-digit int8: acc1 = a1b1; accx = a1b2 + a2b1.
// val = (acc1 + accx/254) * sX_r * tB_n + bias.
// q cols (n0<512): fused norm + bf16 split; k,v cols: fp32 to g_qkv.
// =====================================================================
__device__ __forceinline__ void imma_stage_load(uint32_t sdst, int tid, int m0, int n0, int k0)
{
    #pragma unroll
    for (int j = 0; j < 2; ++j) {
        const int idx = tid + j * 256;
        const int row = idx >> 2, seg = idx & 3;
        const uint32_t d = sdst + (uint32_t)row * 80u + (uint32_t)seg * 16u;
        const size_t ga = (size_t)(m0 + row) * 512 + k0 + seg * 16;
        const size_t gb = (size_t)(n0 + row) * 512 + k0 + seg * 16;
        CPA(d + IA1_O, g_Xa1 + ga);
        CPA(d + IA2_O, g_Xa2 + ga);
        CPA(d + IB1_O, g_Wb1 + gb);
        CPA(d + IB2_O, g_Wb2 + gb);
    }
}

__global__ __launch_bounds__(256, 1) void imma_qkv_kernel(const float* __restrict__ gammaIn)
{
    extern __shared__ char smem[];
    const uint32_t sb = smem_u32(smem);
    const int tid = threadIdx.x, lane = tid & 31, warp = tid >> 5;
    const int wm = warp >> 2, wn = warp & 3;
    const int m0 = blockIdx.y * 128, n0 = blockIdx.x * 128;

    int acc1[4][4][4], accx[4][4][4];
    #pragma unroll
    for (int i = 0; i < 4; ++i)
        #pragma unroll
        for (int j = 0; j < 4; ++j)
            #pragma unroll
            for (int u = 0; u < 4; ++u) { acc1[i][j][u] = 0; accx[i][j][u] = 0; }

    // ldmatrix lane addressing (int8 k32 frags via b16 ldsm)
    const int lrow = (lane & 7) + ((lane >> 3) & 1) * 8;
    const int lbyte = (lane >> 4) * 16;

    imma_stage_load(sb, tid, m0, n0, 0);
    CPC();

    #pragma unroll 1
    for (int c = 0; c < 8; ++c) {
        if (c < 7) {
            imma_stage_load(sb + (uint32_t)((c + 1) & 1) * ISTAGE_B, tid, m0, n0, (c + 1) * 64);
            CPC();
            asm volatile("cp.async.wait_group 1;" ::: "memory");
        } else {
            asm volatile("cp.async.wait_group 0;" ::: "memory");
        }
        __syncthreads();

        const uint32_t s0 = sb + (uint32_t)(c & 1) * ISTAGE_B;
        #pragma unroll
        for (int ks = 0; ks < 2; ++ks) {
            uint32_t a1f[4][4], a2f[4][4];
            #pragma unroll
            for (int mt = 0; mt < 4; ++mt) {
                const uint32_t aoff = (uint32_t)((wm * 64 + mt * 16 + lrow) * 80
                                                 + ks * 32 + lbyte);
                ldsm4(a1f[mt], s0 + IA1_O + aoff);
                ldsm4(a2f[mt], s0 + IA2_O + aoff);
            }
            #pragma unroll
            for (int g = 0; g < 2; ++g) {
                const uint32_t boff = (uint32_t)((wn * 32 + g * 16 + lrow) * 80
                                                 + ks * 32 + lbyte);
                uint32_t b1r[4], b2r[4];
                ldsm4(b1r, s0 + IB1_O + boff);
                ldsm4(b2r, s0 + IB2_O + boff);
                #pragma unroll
                for (int p = 0; p < 2; ++p) {
                    const uint32_t bf1[2] = {b1r[p], b1r[p + 2]};
                    const uint32_t bf2[2] = {b2r[p], b2r[p + 2]};
                    const int nt = 2 * g + p;
                    #pragma unroll
                    for (int mt = 0; mt < 4; ++mt) {
                        imma16832(acc1[mt][nt], a1f[mt], bf1);
                        imma16832(accx[mt][nt], a1f[mt], bf2);
                        imma16832(accx[mt][nt], a2f[mt], bf1);
                    }
                }
            }
        }
        __syncthreads();
    }

    // ---- dequant to fp32 (+bias) ----
    const int r_l = lane >> 2;
    const int cg0 = n0 + wn * 32 + (lane & 3) * 2;
    const float inv254 = 1.0f / 254.0f;

    float sA0[4], sA8[4];
    #pragma unroll
    for (int mt = 0; mt < 4; ++mt) {
        const int rr = m0 + wm * 64 + mt * 16 + r_l;
        sA0[mt] = g_sX[rr];
        sA8[mt] = g_sX[rr + 8];
    }
    float facc[4][4][4];
    #pragma unroll
    for (int nt = 0; nt < 4; ++nt) {
        const int cc = cg0 + nt * 8;
        const float t0 = g_tB[cc], t1 = g_tB[cc + 1];
        const float b0 = g_biasC[cc], b1 = g_biasC[cc + 1];
        #pragma unroll
        for (int mt = 0; mt < 4; ++mt) {
            facc[mt][nt][0] = fmaf(((float)acc1[mt][nt][0] + (float)accx[mt][nt][0] * inv254),
                                   sA0[mt] * t0, b0);
            facc[mt][nt][1] = fmaf(((float)acc1[mt][nt][1] + (float)accx[mt][nt][1] * inv254),
                                   sA0[mt] * t1, b1);
            facc[mt][nt][2] = fmaf(((float)acc1[mt][nt][2] + (float)accx[mt][nt][2] * inv254),
                                   sA8[mt] * t0, b0);
            facc[mt][nt][3] = fmaf(((float)acc1[mt][nt][3] + (float)accx[mt][nt][3] * inv254),
                                   sA8[mt] * t1, b1);
        }
    }

    if (n0 < 512) {
        // fused q-norm: head spans warp pair (wn, wn^1); combine via smem
        float* part = reinterpret_cast<float*>(smem);
        const float gam = gammaIn[(n0 + wn * 32) >> 6];
        float sums[8], sc_arr[8];
        #pragma unroll
        for (int mt = 0; mt < 4; ++mt) {
            #pragma unroll
            for (int z = 0; z < 2; ++z) {
                float s = 0.f;
                #pragma unroll
                for (int nt = 0; nt < 4; ++nt) {
                    float x0 = facc[mt][nt][2 * z], x1 = facc[mt][nt][2 * z + 1];
                    s = fmaf(x0, x0, s); s = fmaf(x1, x1, s);
                }
                s += __shfl_xor_sync(0xffffffffu, s, 1);
                s += __shfl_xor_sync(0xffffffffu, s, 2);
                sums[mt * 2 + z] = s;
            }
        }
        #pragma unroll
        for (int mt = 0; mt < 4; ++mt)
            #pragma unroll
            for (int z = 0; z < 2; ++z)
                if ((lane & 3) == 0) {
                    const int rt = wm * 64 + mt * 16 + z * 8 + r_l;
                    part[rt * 4 + wn] = sums[mt * 2 + z];
                }
        __syncthreads();
        #pragma unroll
        for (int mt = 0; mt < 4; ++mt)
            #pragma unroll
            for (int z = 0; z < 2; ++z) {
                const int rt = wm * 64 + mt * 16 + z * 8 + r_l;
                const float s2 = part[rt * 4 + wn] + part[rt * 4 + (wn ^ 1)];
                sc_arr[mt * 2 + z] = gam / sqrtf(s2);
            }
        #pragma unroll
        for (int mt = 0; mt < 4; ++mt) {
            #pragma unroll
            for (int z = 0; z < 2; ++z) {
                const int rr = m0 + wm * 64 + mt * 16 + z * 8 + r_l;
                const float sc = sc_arr[mt * 2 + z];
                #pragma unroll
                for (int nt = 0; nt < 4; ++nt) {
                    __nv_bfloat16 h0, l0, h1, l1;
                    split1(facc[mt][nt][2 * z] * sc, h0, l0);
                    split1(facc[mt][nt][2 * z + 1] * sc, h1, l1);
                    const uint32_t hw = (uint32_t)__bfloat16_as_ushort(h0)
                                      | ((uint32_t)__bfloat16_as_ushort(h1) << 16);
                    const uint32_t lw = (uint32_t)__bfloat16_as_ushort(l0)
                                      | ((uint32_t)__bfloat16_as_ushort(l1) << 16);
                    const size_t o = (size_t)rr * 512 + cg0 + nt * 8;
                    *reinterpret_cast<uint32_t*>(&g_qsh[o]) = hw;
                    *reinterpret_cast<uint32_t*>(&g_qsl[o]) = lw;
                }
            }
        }
    } else {
        #pragma unroll
        for (int mt = 0; mt < 4; ++mt) {
            #pragma unroll
            for (int nt = 0; nt < 4; ++nt) {
                const int rr = m0 + wm * 64 + mt * 16 + r_l;
                const int cc = cg0 + nt * 8;
                const int mat = cc >> 9, c2 = cc & 511;
                float* dst = g_qkv + (size_t)mat * BN_ROWS * 512 + (size_t)rr * 512 + c2;
                *reinterpret_cast<float2*>(dst) = make_float2(facc[mt][nt][0], facc[mt][nt][1]);
                *reinterpret_cast<float2*>(dst + 8 * 512) = make_float2(facc[mt][nt][2], facc[mt][nt][3]);
            }
        }
    }
}

// =====================================================================
// Final bf16 HMMA GEMM (unchanged from R6, final-only path)
// =====================================================================
__device__ __forceinline__ void hmma_stage_load(
    uint32_t sdst,
    const __nv_bfloat16* __restrict__ Ah, const __nv_bfloat16* __restrict__ Al,
    const __nv_bfloat16* __restrict__ Bh, const __nv_bfloat16* __restrict__ Bl,
    int tid, int m0, int n0, int k0)
{
    #pragma unroll
    for (int j = 0; j < 2; ++j) {
        const int idx = tid + j * 256;
        const int row = idx >> 2, seg = idx & 3;
        const uint32_t d = sdst + (uint32_t)row * 80u + (uint32_t)seg * 16u;
        const size_t ga = (size_t)(m0 + row) * 512 + k0 + seg * 8;
        const size_t gb = (size_t)(n0 + row) * 512 + k0 + seg * 8;
        CPA(d + AH_O, Ah + ga);
        CPA(d + AL_O, Al + ga);
        CPA(d + BH_O, Bh + gb);
        CPA(d + BL_O, Bl + gb);
    }
}

__global__ __launch_bounds__(256, 2) void hmma_final_kernel(
    const float* __restrict__ biasIn, float* __restrict__ Cout)
{
    extern __shared__ char smem[];
    const uint32_t sb = smem_u32(smem);
    const int tid = threadIdx.x, lane = tid & 31, warp = tid >> 5;
    const int wm = warp >> 2, wn = warp & 3;
    const int m0 = blockIdx.y * 128, n0 = blockIdx.x * 128;

    const __nv_bfloat16* Agh = g_qsh;
    const __nv_bfloat16* Agl = g_qsl;
    const size_t boff = (size_t)(m0 >> 13) * 512 * 512;
    const __nv_bfloat16* Bgh = g_Mth + boff;
    const __nv_bfloat16* Bgl = g_Mtl + boff;

    float acc[4][4][4];
    #pragma unroll
    for (int i = 0; i < 4; ++i)
        #pragma unroll
        for (int j = 0; j < 4; ++j)
            #pragma unroll
            for (int u = 0; u < 4; ++u) acc[i][j][u] = 0.f;

    const int a_r  = lane & 15;
    const int a_c  = (lane >> 4) << 3;
    const int bg   = lane >> 3;
    const int b_nr = ((bg & 2) << 2) + (lane & 7);
    const int b_ka = (bg & 1) << 3;

    hmma_stage_load(sb, Agh, Agl, Bgh, Bgl, tid, m0, n0, 0);
    CPC();

    #pragma unroll 1
    for (int c = 0; c < 16; ++c) {
        if (c < 15) {
            hmma_stage_load(sb + (uint32_t)((c + 1) & 1) * STAGE_B, Agh, Agl, Bgh, Bgl,
                            tid, m0, n0, (c + 1) * 32);
            CPC();
            asm volatile("cp.async.wait_group 1;" ::: "memory");
        } else {
            asm volatile("cp.async.wait_group 0;" ::: "memory");
        }
        __syncthreads();

        const uint32_t s0 = sb + (uint32_t)(c & 1) * STAGE_B;
        #pragma unroll
        for (int ks = 0; ks < 2; ++ks) {
            uint32_t ah[4][4], al[4][4];
            #pragma unroll
            for (int mt = 0; mt < 4; ++mt) {
                const uint32_t aoff = (uint32_t)((wm * 64 + mt * 16 + a_r) * 80
                                                 + (ks * 16 + a_c) * 2);
                ldsm4(ah[mt], s0 + AH_O + aoff);
                ldsm4(al[mt], s0 + AL_O + aoff);
            }
            #pragma unroll
            for (int g = 0; g < 2; ++g) {
                const uint32_t boff2 = (uint32_t)((wn * 32 + g * 16 + b_nr) * 80
                                                  + (ks * 16 + b_ka) * 2);
                uint32_t bh4[4], bl4[4];
                ldsm4(bh4, s0 + BH_O + boff2);
                ldsm4(bl4, s0 + BL_O + boff2);
                #pragma unroll
                for (int mt = 0; mt < 4; ++mt) {
                    mma16816(acc[mt][2 * g],     ah[mt], bh4);
                    mma16816(acc[mt][2 * g],     ah[mt], bl4);
                    mma16816(acc[mt][2 * g],     al[mt], bh4);
                    mma16816(acc[mt][2 * g + 1], ah[mt], bh4 + 2);
                    mma16816(acc[mt][2 * g + 1], ah[mt], bl4 + 2);
                    mma16816(acc[mt][2 * g + 1], al[mt], bh4 + 2);
                }
            }
        }
        __syncthreads();
    }

    const int r_l = lane >> 2;
    const int cg0 = n0 + wn * 32 + (lane & 3) * 2;
    #pragma unroll
    for (int mt = 0; mt < 4; ++mt) {
        #pragma unroll
        for (int nt = 0; nt < 4; ++nt) {
            const int rr = m0 + wm * 64 + mt * 16 + r_l;
            const int cc = cg0 + nt * 8;
            const float bx = biasIn[cc], by = biasIn[cc + 1];
            float* dst = Cout + (size_t)rr * 512 + cc;
            *reinterpret_cast<float2*>(dst) = make_float2(acc[mt][nt][0] + bx, acc[mt][nt][1] + by);
            *reinterpret_cast<float2*>(dst + 8 * 512) = make_float2(acc[mt][nt][2] + bx, acc[mt][nt][3] + by);
        }
    }
}

// =====================================================================
// kv partial outer products (fp32 SIMT, memory-bound) — unchanged
// =====================================================================
__global__ __launch_bounds__(256) void kv_partial_kernel()
{
    const int chunk = blockIdx.x;
    const int bh    = blockIdx.y;
    const int b     = bh >> 3;
    const int h     = bh & 7;

    const float* kk = g_qkv + (size_t)1 * BN_ROWS * D_;
    const float* vv = g_qkv + (size_t)2 * BN_ROWS * D_;

    __shared__ float ks[16][68];
    __shared__ float vs[16][68];

    const int tid = threadIdx.x;
    const int lr  = tid >> 4;
    const int lc4 = (tid & 15) << 2;
    const int tx  = tid & 15;
    const int ty  = tid >> 4;

    float acc[4][4];
    #pragma unroll
    for (int i = 0; i < 4; i++)
        #pragma unroll
        for (int j = 0; j < 4; j++) acc[i][j] = 0.f;

    const size_t base = (size_t)b * N_ * D_ + h * 64;
    const int nbeg = chunk * 1024;
    for (int n0 = nbeg; n0 < nbeg + 1024; n0 += 16) {
        const size_t off = base + (size_t)(n0 + lr) * D_ + lc4;
        *reinterpret_cast<float4*>(&ks[lr][lc4]) = *reinterpret_cast<const float4*>(&kk[off]);
        *reinterpret_cast<float4*>(&vs[lr][lc4]) = *reinterpret_cast<const float4*>(&vv[off]);
        __syncthreads();
        #pragma unroll
        for (int nn = 0; nn < 16; nn++) {
            float a[4], w[4];
            #pragma unroll
            for (int i = 0; i < 4; i++) a[i] = ks[nn][ty * 4 + i];
            #pragma unroll
            for (int j = 0; j < 4; j++) w[j] = vs[nn][tx * 4 + j];
            #pragma unroll
            for (int i = 0; i < 4; i++)
                #pragma unroll
                for (int j = 0; j < 4; j++) acc[i][j] = fmaf(a[i], w[j], acc[i][j]);
        }
        __syncthreads();
    }

    float* P = g_kvp + ((size_t)bh * 8 + chunk) * 4096;
    #pragma unroll
    for (int i = 0; i < 4; i++) {
        float4 o = make_float4(acc[i][0], acc[i][1], acc[i][2], acc[i][3]);
        *reinterpret_cast<float4*>(&P[(ty * 4 + i) * 64 + tx * 4]) = o;
    }
}

// =====================================================================
// kv reduce + normalize + fold Wo -> Mt[b][d][k] — unchanged
// =====================================================================
__global__ __launch_bounds__(256) void kv_reduce_M_kernel(
    const float* __restrict__ Wo, const float* __restrict__ gamma)
{
    const int bh = blockIdx.x;
    const int b  = bh >> 3;
    const int h  = bh & 7;

    __shared__ float kvs[64][65];
    __shared__ float wos[64][65];
    __shared__ float mts[64][65];
    __shared__ float rs[64];

    const int tid = threadIdx.x;

    for (int idx = tid; idx < 4096; idx += 256) {
        float s = 0.f;
        #pragma unroll
        for (int p = 0; p < 8; p++) s += g_kvp[((size_t)bh * 8 + p) * 4096 + idx];
        kvs[idx >> 6][idx & 63] = s;
    }
    __syncthreads();

    if (tid < 64) {
        float s = 0.f;
        #pragma unroll
        for (int c = 0; c < 64; c++) { float x = kvs[tid][c]; s = fmaf(x, x, s); }
        rs[tid] = gamma[h] / sqrtf(s);
    }
    __syncthreads();

    const int tx = tid & 15;
    const int ty = tid >> 4;
    const int dcol = tid >> 2;
    const int seg  = (tid & 3) * 16;

    for (int dt = 0; dt < 8; dt++) {
        const int d0 = dt * 64;
        for (int idx = tid; idx < 4096; idx += 256) {
            const int dv = idx >> 6, dd = idx & 63;
            wos[dv][dd] = Wo[(size_t)(h * 64 + dv) * D_ + d0 + dd];
        }
        __syncthreads();

        float acc[4][4];
        #pragma unroll
        for (int i = 0; i < 4; i++)
            #pragma unroll
            for (int j = 0; j < 4; j++) acc[i][j] = 0.f;

        #pragma unroll 8
        for (int dv = 0; dv < 64; dv++) {
            float a[4], w[4];
            #pragma unroll
            for (int i = 0; i < 4; i++) a[i] = kvs[ty * 4 + i][dv];
            #pragma unroll
            for (int j = 0; j < 4; j++) w[j] = wos[dv][tx * 4 + j];
            #pragma unroll
            for (int i = 0; i < 4; i++)
                #pragma unroll
                for (int j = 0; j < 4; j++) acc[i][j] = fmaf(a[i], w[j], acc[i][j]);
        }

        #pragma unroll
        for (int i = 0; i < 4; i++) {
            const float sc = rs[ty * 4 + i];
            #pragma unroll
            for (int j = 0; j < 4; j++) mts[ty * 4 + i][tx * 4 + j] = acc[i][j] * sc;
        }
        __syncthreads();

        uint32_t hw[8], lw[8];
        #pragma unroll
        for (int u = 0; u < 8; ++u) {
            float x0 = mts[seg + 2 * u][dcol];
            float x1 = mts[seg + 2 * u + 1][dcol];
            __nv_bfloat16 h0, l0, h1, l1;
            split1(x0, h0, l0); split1(x1, h1, l1);
            hw[u] = (uint32_t)__bfloat16_as_ushort(h0) | ((uint32_t)__bfloat16_as_ushort(h1) << 16);
            lw[u] = (uint32_t)__bfloat16_as_ushort(l0) | ((uint32_t)__bfloat16_as_ushort(l1) << 16);
        }
        const size_t o = ((size_t)b * 512 + d0 + dcol) * 512 + h * 64 + seg;
        uint4* ph = reinterpret_cast<uint4*>(&g_Mth[o]);
        uint4* pl = reinterpret_cast<uint4*>(&g_Mtl[o]);
        ph[0] = make_uint4(hw[0], hw[1], hw[2], hw[3]);
        ph[1] = make_uint4(hw[4], hw[5], hw[6], hw[7]);
        pl[0] = make_uint4(lw[0], lw[1], lw[2], lw[3]);
        pl[1] = make_uint4(lw[4], lw[5], lw[6], lw[7]);
        __syncthreads();
    }
}

// =====================================================================
extern "C" void kernel_launch(void* const* d_in, const int* in_sizes, int n_in,
                              void* d_out, int out_size)
{
    const float* X     = (const float*)d_in[0];
    const float* Wq    = (const float*)d_in[1];
    const float* bq    = (const float*)d_in[2];
    const float* Wk    = (const float*)d_in[3];
    const float* bk    = (const float*)d_in[4];
    const float* Wv    = (const float*)d_in[5];
    const float* bv    = (const float*)d_in[6];
    const float* Wo    = (const float*)d_in[7];
    const float* bo    = (const float*)d_in[8];
    const float* gamma = (const float*)d_in[9];
    float* out = (float*)d_out;

    cudaFuncSetAttribute(imma_qkv_kernel,  cudaFuncAttributeMaxDynamicSharedMemorySize, IMMA_SMEM);
    cudaFuncSetAttribute(hmma_final_kernel, cudaFuncAttributeMaxDynamicSharedMemorySize, HMMA_SMEM);

    // 1) quantize X (2-digit int8, per-row scale)
    quant_x_kernel<<<8192, 256>>>(X);
    // 2) quantize W^T (per-n scale)
    quant_w_kernel<<<192, 256>>>(Wq, Wk, Wv);
    // 3) pack biases
    pack_bias_kernel<<<6, 256>>>(bq, bk, bv);
    // 4) QKV projection on int8 tensor cores + fused q-norm epilogue  [ncu slot]
    imma_qkv_kernel<<<dim3(12, 512), 256, IMMA_SMEM>>>(gamma);
    // 5) kv partial outer products
    kv_partial_kernel<<<dim3(8, 64), 256>>>();
    // 6) reduce kv, normalize, fold Wo -> Mt (bf16 hi/lo)
    kv_reduce_M_kernel<<<64, 256>>>(Wo, gamma);
    // 7) out = q_n @ Mt^T + bo (bf16 HMMA)
    hmma_final_kernel<<<dim3(4, 512), 256, HMMA_SMEM>>>(bo, out);
}

// round 8
// speedup vs baseline: 2.2627x; 2.2627x over previous
#include <cuda_runtime.h>
#include <cuda_bf16.h>
#include <math.h>
#include <stdint.h>

#define B_   8
#define N_   8192
#define D_   512
#define H_   8
#define BN_ROWS 65536

// ---------------- scratch (static device arrays) ----------------
__device__ float g_qkv[(size_t)3 * BN_ROWS * D_];            // [unused q] | k | v fp32
__device__ __nv_bfloat16 g_Xh[(size_t)BN_ROWS * D_];
__device__ __nv_bfloat16 g_Xl[(size_t)BN_ROWS * D_];
__device__ __nv_bfloat16 g_qsh[(size_t)BN_ROWS * D_];        // q_n split
__device__ __nv_bfloat16 g_qsl[(size_t)BN_ROWS * D_];
__device__ __nv_bfloat16 g_Bth[1536 * 512];                  // [n][k] Wq|Wk|Wv^T hi
__device__ __nv_bfloat16 g_Btl[1536 * 512];
__device__ float g_biasC[1536];
__device__ float g_kvp[(size_t)64 * 8 * 4096];
__device__ __nv_bfloat16 g_Mth[(size_t)B_ * 512 * 512];      // Mt[b][d][k] hi
__device__ __nv_bfloat16 g_Mtl[(size_t)B_ * 512 * 512];

// ---------------- helpers ----------------
__device__ __forceinline__ uint32_t smem_u32(const void* p) {
    uint32_t a;
    asm("{ .reg .u64 t; cvta.to.shared.u64 t, %1; cvt.u32.u64 %0, t; }" : "=r"(a) : "l"(p));
    return a;
}
__device__ __forceinline__ void ldsm4(uint32_t* r, uint32_t a) {
    asm volatile("ldmatrix.sync.aligned.m8n8.x4.shared.b16 {%0,%1,%2,%3}, [%4];"
                 : "=r"(r[0]), "=r"(r[1]), "=r"(r[2]), "=r"(r[3]) : "r"(a));
}
// NOTE: non-volatile — pure register function; lets ptxas schedule MMAs.
__device__ __forceinline__ void mma16816(float* c, const uint32_t* a, const uint32_t* b) {
    asm("mma.sync.aligned.m16n8k16.row.col.f32.bf16.bf16.f32 "
        "{%0,%1,%2,%3}, {%4,%5,%6,%7}, {%8,%9}, {%0,%1,%2,%3};"
        : "+f"(c[0]), "+f"(c[1]), "+f"(c[2]), "+f"(c[3])
        : "r"(a[0]), "r"(a[1]), "r"(a[2]), "r"(a[3]), "r"(b[0]), "r"(b[1]));
}
#define CPA(d, s) asm volatile("cp.async.cg.shared.global [%0], [%1], 16;" :: "r"(d), "l"(s))
#define CPC()     asm volatile("cp.async.commit_group;" ::: "memory")

__device__ __forceinline__ void split1(float x, __nv_bfloat16& h, __nv_bfloat16& l) {
    h = __float2bfloat16(x);
    l = __float2bfloat16(x - __bfloat162float(h));
}

// SMEM stage layout (bf16, row stride 72 elems = 144B)
#define AH_O 0u
#define AL_O 18432u
#define BH_O 36864u
#define BL_O 73728u
#define STAGE_B  110592u
#define DYN_SMEM (2 * 110592)

// =====================================================================
// split_x: X fp32 -> Xh, Xl bf16 (two halves, keeps GEMM at ncu launch #4)
// =====================================================================
__global__ __launch_bounds__(256) void split_x_kernel(const float* __restrict__ X, size_t base)
{
    const size_t i = base + ((size_t)blockIdx.x * 256 + threadIdx.x) * 8;
    float4 v0 = *reinterpret_cast<const float4*>(X + i);
    float4 v1 = *reinterpret_cast<const float4*>(X + i + 4);
    float v[8] = {v0.x, v0.y, v0.z, v0.w, v1.x, v1.y, v1.z, v1.w};
    ushort hh[8], ll[8];
    #pragma unroll
    for (int j = 0; j < 8; ++j) {
        __nv_bfloat16 h, l; split1(v[j], h, l);
        hh[j] = __bfloat16_as_ushort(h); ll[j] = __bfloat16_as_ushort(l);
    }
    uint4 hv, lv;
    hv.x = hh[0] | ((uint32_t)hh[1] << 16); hv.y = hh[2] | ((uint32_t)hh[3] << 16);
    hv.z = hh[4] | ((uint32_t)hh[5] << 16); hv.w = hh[6] | ((uint32_t)hh[7] << 16);
    lv.x = ll[0] | ((uint32_t)ll[1] << 16); lv.y = ll[2] | ((uint32_t)ll[3] << 16);
    lv.z = ll[4] | ((uint32_t)ll[5] << 16); lv.w = ll[6] | ((uint32_t)ll[7] << 16);
    *reinterpret_cast<uint4*>(&g_Xh[i]) = hv;
    *reinterpret_cast<uint4*>(&g_Xl[i]) = lv;
}

// =====================================================================
// prep_w: transpose + split weights into g_Bth/g_Btl [n][k]; pack bias
// =====================================================================
__global__ void prep_w_kernel(
    const float* __restrict__ Wq, const float* __restrict__ Wk, const float* __restrict__ Wv,
    const float* __restrict__ bq, const float* __restrict__ bk, const float* __restrict__ bv)
{
    __shared__ float tile[32][33];
    const int k0 = blockIdx.x * 32, n0g = blockIdx.y * 32;
    const float* W; const float* bias;
    if (n0g < 512)       { W = Wq; bias = bq; }
    else if (n0g < 1024) { W = Wk; bias = bk; }
    else                 { W = Wv; bias = bv; }
    const int nn0 = n0g & 511;
    const int tx = threadIdx.x, ty = threadIdx.y;
    #pragma unroll
    for (int i = 0; i < 4; ++i)
        tile[ty + i * 8][tx] = W[(size_t)(k0 + ty + i * 8) * 512 + nn0 + tx];
    __syncthreads();
    #pragma unroll
    for (int i = 0; i < 4; ++i) {
        float x = tile[tx][ty + i * 8];
        __nv_bfloat16 h, l; split1(x, h, l);
        size_t o = (size_t)(n0g + ty + i * 8) * 512 + k0 + tx;
        g_Bth[o] = h; g_Btl[o] = l;
    }
    if (blockIdx.x == 0 && ty == 0) g_biasC[n0g + tx] = bias[nn0 + tx];
}

// =====================================================================
// HMMA GEMM: CTA tile 128x256, warp tile 64x64 (8 warps = 2M x 4N).
// C = A @ B^T, 3-term bf16 split. A[m][k], B[n][k], k contiguous.
// MMA emission: 3 passes (hh, hl, lh) over 8 distinct accumulators per
// N-group -> same-acc reuse distance 8 (was 1), hides HMMA RAW latency.
// =====================================================================
__device__ __forceinline__ void stage_load(
    uint32_t sdst,
    const __nv_bfloat16* __restrict__ Ah, const __nv_bfloat16* __restrict__ Al,
    const __nv_bfloat16* __restrict__ Bh, const __nv_bfloat16* __restrict__ Bl,
    int tid, int m0, int n0, int k0)
{
    #pragma unroll
    for (int j = 0; j < 4; ++j) {                 // A: 128 rows x 8 segs
        const int idx = tid + j * 256;
        const int row = idx >> 3, seg = idx & 7;
        const uint32_t d = sdst + (uint32_t)row * 144u + (uint32_t)seg * 16u;
        const size_t g = (size_t)(m0 + row) * 512 + k0 + seg * 8;
        CPA(d + AH_O, Ah + g);
        CPA(d + AL_O, Al + g);
    }
    #pragma unroll
    for (int j = 0; j < 8; ++j) {                 // B: 256 rows x 8 segs
        const int idx = tid + j * 256;
        const int row = idx >> 3, seg = idx & 7;
        const uint32_t d = sdst + (uint32_t)row * 144u + (uint32_t)seg * 16u;
        const size_t g = (size_t)(n0 + row) * 512 + k0 + seg * 8;
        CPA(d + BH_O, Bh + g);
        CPA(d + BL_O, Bl + g);
    }
}

template<bool QKV>
__global__ __launch_bounds__(256, 1) void hmma_gemm_kernel(
    const float* __restrict__ biasIn, const float* __restrict__ gammaIn,
    float* __restrict__ Cout)
{
    extern __shared__ char smem[];
    const uint32_t sb = smem_u32(smem);
    const int tid = threadIdx.x, lane = tid & 31, warp = tid >> 5;
    const int wm = warp >> 2, wn = warp & 3;      // 2 x 4 warp grid
    const int m0 = blockIdx.y * 128, n0 = blockIdx.x * 256;

    const __nv_bfloat16 *Agh, *Agl, *Bgh, *Bgl;
    if (QKV) { Agh = g_Xh; Agl = g_Xl; Bgh = g_Bth; Bgl = g_Btl; }
    else {
        Agh = g_qsh; Agl = g_qsl;
        const size_t boff = (size_t)(m0 >> 13) * 512 * 512;
        Bgh = g_Mth + boff; Bgl = g_Mtl + boff;
    }

    float acc[4][8][4];
    #pragma unroll
    for (int i = 0; i < 4; ++i)
        #pragma unroll
        for (int j = 0; j < 8; ++j)
            #pragma unroll
            for (int u = 0; u < 4; ++u) acc[i][j][u] = 0.f;

    // ldmatrix lane addressing
    const int a_r  = lane & 15;
    const int a_c  = (lane >> 4) << 3;            // 0 or 8
    const int bg   = lane >> 3;
    const int b_nr = ((bg & 2) << 2) + (lane & 7);
    const int b_ka = (bg & 1) << 3;

    stage_load(sb, Agh, Agl, Bgh, Bgl, tid, m0, n0, 0);
    CPC();

    #pragma unroll 1
    for (int c = 0; c < 8; ++c) {
        if (c < 7) {
            stage_load(sb + (uint32_t)((c + 1) & 1) * STAGE_B, Agh, Agl, Bgh, Bgl,
                       tid, m0, n0, (c + 1) * 64);
            CPC();
            asm volatile("cp.async.wait_group 1;" ::: "memory");
        } else {
            asm volatile("cp.async.wait_group 0;" ::: "memory");
        }
        __syncthreads();

        const uint32_t s0 = sb + (uint32_t)(c & 1) * STAGE_B;
        #pragma unroll
        for (int ks = 0; ks < 4; ++ks) {
            uint32_t ah[4][4], al[4][4];
            #pragma unroll
            for (int mt = 0; mt < 4; ++mt) {
                const uint32_t aoff = (uint32_t)((wm * 64 + mt * 16 + a_r) * 144
                                                 + (ks * 16 + a_c) * 2);
                ldsm4(ah[mt], s0 + AH_O + aoff);
                ldsm4(al[mt], s0 + AL_O + aoff);
            }
            #pragma unroll
            for (int g = 0; g < 4; ++g) {
                const uint32_t boff = (uint32_t)((wn * 64 + g * 16 + b_nr) * 144
                                                 + (ks * 16 + b_ka) * 2);
                uint32_t bh4[4], bl4[4];
                ldsm4(bh4, s0 + BH_O + boff);
                ldsm4(bl4, s0 + BL_O + boff);
                // pass 1: hh over 8 distinct accumulators
                #pragma unroll
                for (int mt = 0; mt < 4; ++mt) {
                    mma16816(acc[mt][2 * g],     ah[mt], bh4);
                    mma16816(acc[mt][2 * g + 1], ah[mt], bh4 + 2);
                }
                // pass 2: hl
                #pragma unroll
                for (int mt = 0; mt < 4; ++mt) {
                    mma16816(acc[mt][2 * g],     ah[mt], bl4);
                    mma16816(acc[mt][2 * g + 1], ah[mt], bl4 + 2);
                }
                // pass 3: lh
                #pragma unroll
                for (int mt = 0; mt < 4; ++mt) {
                    mma16816(acc[mt][2 * g],     al[mt], bh4);
                    mma16816(acc[mt][2 * g + 1], al[mt], bh4 + 2);
                }
            }
        }
        __syncthreads();
    }

    // ---- epilogue ----
    const int r0 = m0 + wm * 64 + (lane >> 2);
    const int c0base = wn * 64 + (lane & 3) * 2;     // within-tile col
    const int cg0 = n0 + c0base;                     // global col

    if (QKV && cg0 < 512) {
        // fused q-norm epilogue: this warp's 64 cols = one head
        const int h = (n0 + wn * 64) >> 6;
        const float gam = gammaIn[h];
        #pragma unroll
        for (int mt = 0; mt < 4; ++mt) {
            #pragma unroll
            for (int z = 0; z < 2; ++z) {
                const int rr = r0 + mt * 16 + z * 8;
                float vals[16];
                float s = 0.f;
                #pragma unroll
                for (int nt = 0; nt < 8; ++nt) {
                    const int cc = cg0 + nt * 8;
                    float x0 = acc[mt][nt][2 * z]     + g_biasC[cc];
                    float x1 = acc[mt][nt][2 * z + 1] + g_biasC[cc + 1];
                    vals[2 * nt] = x0; vals[2 * nt + 1] = x1;
                    s = fmaf(x0, x0, s); s = fmaf(x1, x1, s);
                }
                s += __shfl_xor_sync(0xffffffffu, s, 1);
                s += __shfl_xor_sync(0xffffffffu, s, 2);
                const float sc = gam / sqrtf(s);
                #pragma unroll
                for (int nt = 0; nt < 8; ++nt) {
                    __nv_bfloat16 h0, l0, h1, l1;
                    split1(vals[2 * nt] * sc, h0, l0);
                    split1(vals[2 * nt + 1] * sc, h1, l1);
                    const uint32_t hw = (uint32_t)__bfloat16_as_ushort(h0)
                                      | ((uint32_t)__bfloat16_as_ushort(h1) << 16);
                    const uint32_t lw = (uint32_t)__bfloat16_as_ushort(l0)
                                      | ((uint32_t)__bfloat16_as_ushort(l1) << 16);
                    const size_t o = (size_t)rr * 512 + cg0 + nt * 8;
                    *reinterpret_cast<uint32_t*>(&g_qsh[o]) = hw;
                    *reinterpret_cast<uint32_t*>(&g_qsl[o]) = lw;
                }
            }
        }
    } else {
        #pragma unroll
        for (int mt = 0; mt < 4; ++mt) {
            #pragma unroll
            for (int nt = 0; nt < 8; ++nt) {
                const int rr = r0 + mt * 16;
                const int cc = cg0 + nt * 8;
                float bx, by;
                float* dst;
                if (QKV) {
                    const int mat = cc >> 9, c2 = cc & 511;
                    bx = g_biasC[cc]; by = g_biasC[cc + 1];
                    dst = g_qkv + (size_t)mat * BN_ROWS * 512 + (size_t)rr * 512 + c2;
                } else {
                    bx = biasIn[cc]; by = biasIn[cc + 1];
                    dst = Cout + (size_t)rr * 512 + cc;
                }
                float2 v0 = make_float2(acc[mt][nt][0] + bx, acc[mt][nt][1] + by);
                float2 v1 = make_float2(acc[mt][nt][2] + bx, acc[mt][nt][3] + by);
                *reinterpret_cast<float2*>(dst) = v0;
                *reinterpret_cast<float2*>(dst + 8 * 512) = v1;
            }
        }
    }
}

// =====================================================================
// kv partial outer products (fp32 SIMT, memory-bound)
// =====================================================================
__global__ __launch_bounds__(256) void kv_partial_kernel()
{
    const int chunk = blockIdx.x;
    const int bh    = blockIdx.y;
    const int b     = bh >> 3;
    const int h     = bh & 7;

    const float* kk = g_qkv + (size_t)1 * BN_ROWS * D_;
    const float* vv = g_qkv + (size_t)2 * BN_ROWS * D_;

    __shared__ float ks[16][68];
    __shared__ float vs[16][68];

    const int tid = threadIdx.x;
    const int lr  = tid >> 4;
    const int lc4 = (tid & 15) << 2;
    const int tx  = tid & 15;
    const int ty  = tid >> 4;

    float acc[4][4];
    #pragma unroll
    for (int i = 0; i < 4; i++)
        #pragma unroll
        for (int j = 0; j < 4; j++) acc[i][j] = 0.f;

    const size_t base = (size_t)b * N_ * D_ + h * 64;
    const int nbeg = chunk * 1024;
    for (int n0 = nbeg; n0 < nbeg + 1024; n0 += 16) {
        const size_t off = base + (size_t)(n0 + lr) * D_ + lc4;
        *reinterpret_cast<float4*>(&ks[lr][lc4]) = *reinterpret_cast<const float4*>(&kk[off]);
        *reinterpret_cast<float4*>(&vs[lr][lc4]) = *reinterpret_cast<const float4*>(&vv[off]);
        __syncthreads();
        #pragma unroll
        for (int nn = 0; nn < 16; nn++) {
            float a[4], w[4];
            #pragma unroll
            for (int i = 0; i < 4; i++) a[i] = ks[nn][ty * 4 + i];
            #pragma unroll
            for (int j = 0; j < 4; j++) w[j] = vs[nn][tx * 4 + j];
            #pragma unroll
            for (int i = 0; i < 4; i++)
                #pragma unroll
                for (int j = 0; j < 4; j++) acc[i][j] = fmaf(a[i], w[j], acc[i][j]);
        }
        __syncthreads();
    }

    float* P = g_kvp + ((size_t)bh * 8 + chunk) * 4096;
    #pragma unroll
    for (int i = 0; i < 4; i++) {
        float4 o = make_float4(acc[i][0], acc[i][1], acc[i][2], acc[i][3]);
        *reinterpret_cast<float4*>(&P[(ty * 4 + i) * 64 + tx * 4]) = o;
    }
}

// =====================================================================
// kv reduce + normalize + fold Wo -> Mt[b][d][k] (transposed, bf16 hi/lo)
// =====================================================================
__global__ __launch_bounds__(256) void kv_reduce_M_kernel(
    const float* __restrict__ Wo, const float* __restrict__ gamma)
{
    const int bh = blockIdx.x;
    const int b  = bh >> 3;
    const int h  = bh & 7;

    __shared__ float kvs[64][65];
    __shared__ float wos[64][65];
    __shared__ float mts[64][65];
    __shared__ float rs[64];

    const int tid = threadIdx.x;

    for (int idx = tid; idx < 4096; idx += 256) {
        float s = 0.f;
        #pragma unroll
        for (int p = 0; p < 8; p++) s += g_kvp[((size_t)bh * 8 + p) * 4096 + idx];
        kvs[idx >> 6][idx & 63] = s;
    }
    __syncthreads();

    if (tid < 64) {
        float s = 0.f;
        #pragma unroll
        for (int c = 0; c < 64; c++) { float x = kvs[tid][c]; s = fmaf(x, x, s); }
        rs[tid] = gamma[h] / sqrtf(s);
    }
    __syncthreads();

    const int tx = tid & 15;
    const int ty = tid >> 4;
    const int dcol = tid >> 2;
    const int seg  = (tid & 3) * 16;

    for (int dt = 0; dt < 8; dt++) {
        const int d0 = dt * 64;
        for (int idx = tid; idx < 4096; idx += 256) {
            const int dv = idx >> 6, dd = idx & 63;
            wos[dv][dd] = Wo[(size_t)(h * 64 + dv) * D_ + d0 + dd];
        }
        __syncthreads();

        float acc[4][4];
        #pragma unroll
        for (int i = 0; i < 4; i++)
            #pragma unroll
            for (int j = 0; j < 4; j++) acc[i][j] = 0.f;

        #pragma unroll 8
        for (int dv = 0; dv < 64; dv++) {
            float a[4], w[4];
            #pragma unroll
            for (int i = 0; i < 4; i++) a[i] = kvs[ty * 4 + i][dv];
            #pragma unroll
            for (int j = 0; j < 4; j++) w[j] = wos[dv][tx * 4 + j];
            #pragma unroll
            for (int i = 0; i < 4; i++)
                #pragma unroll
                for (int j = 0; j < 4; j++) acc[i][j] = fmaf(a[i], w[j], acc[i][j]);
        }

        #pragma unroll
        for (int i = 0; i < 4; i++) {
            const float sc = rs[ty * 4 + i];
            #pragma unroll
            for (int j = 0; j < 4; j++) mts[ty * 4 + i][tx * 4 + j] = acc[i][j] * sc;
        }
        __syncthreads();

        uint32_t hw[8], lw[8];
        #pragma unroll
        for (int u = 0; u < 8; ++u) {
            float x0 = mts[seg + 2 * u][dcol];
            float x1 = mts[seg + 2 * u + 1][dcol];
            __nv_bfloat16 h0, l0, h1, l1;
            split1(x0, h0, l0); split1(x1, h1, l1);
            hw[u] = (uint32_t)__bfloat16_as_ushort(h0) | ((uint32_t)__bfloat16_as_ushort(h1) << 16);
            lw[u] = (uint32_t)__bfloat16_as_ushort(l0) | ((uint32_t)__bfloat16_as_ushort(l1) << 16);
        }
        const size_t o = ((size_t)b * 512 + d0 + dcol) * 512 + h * 64 + seg;
        uint4* ph = reinterpret_cast<uint4*>(&g_Mth[o]);
        uint4* pl = reinterpret_cast<uint4*>(&g_Mtl[o]);
        ph[0] = make_uint4(hw[0], hw[1], hw[2], hw[3]);
        ph[1] = make_uint4(hw[4], hw[5], hw[6], hw[7]);
        pl[0] = make_uint4(lw[0], lw[1], lw[2], lw[3]);
        pl[1] = make_uint4(lw[4], lw[5], lw[6], lw[7]);
        __syncthreads();
    }
}

// =====================================================================
extern "C" void kernel_launch(void* const* d_in, const int* in_sizes, int n_in,
                              void* d_out, int out_size)
{
    const float* X     = (const float*)d_in[0];
    const float* Wq    = (const float*)d_in[1];
    const float* bq    = (const float*)d_in[2];
    const float* Wk    = (const float*)d_in[3];
    const float* bk    = (const float*)d_in[4];
    const float* Wv    = (const float*)d_in[5];
    const float* bv    = (const float*)d_in[6];
    const float* Wo    = (const float*)d_in[7];
    const float* bo    = (const float*)d_in[8];
    const float* gamma = (const float*)d_in[9];
    float* out = (float*)d_out;

    cudaFuncSetAttribute(hmma_gemm_kernel<true>,  cudaFuncAttributeMaxDynamicSharedMemorySize, DYN_SMEM);
    cudaFuncSetAttribute(hmma_gemm_kernel<false>, cudaFuncAttributeMaxDynamicSharedMemorySize, DYN_SMEM);

    // 1+2) split X into bf16 hi/lo (two halves -> GEMM lands at launch #4 for ncu)
    split_x_kernel<<<8192, 256>>>(X, 0);
    split_x_kernel<<<8192, 256>>>(X, (size_t)16777216);
    // 3) transpose+split weights, pack biases
    prep_w_kernel<<<dim3(16, 48), dim3(32, 8)>>>(Wq, Wk, Wv, bq, bk, bv);
    // 4) fused QKV projection (HMMA) + fused q-norm epilogue   [ncu slot]
    hmma_gemm_kernel<true><<<dim3(6, 512), 256, DYN_SMEM>>>(nullptr, gamma, nullptr);
    // 5) kv partial outer products
    kv_partial_kernel<<<dim3(8, 64), 256>>>();
    // 6) reduce kv, normalize, fold Wo -> Mt (bf16 hi/lo)
    kv_reduce_M_kernel<<<64, 256>>>(Wo, gamma);
    // 7) out = q_n @ Mt^T + bo on tensor cores
    hmma_gemm_kernel<false><<<dim3(2, 512), 256, DYN_SMEM>>>(bo, nullptr, out);
}